// round 5
// baseline (speedup 1.0000x reference)
#include <cuda_runtime.h>
#include <cstdint>
#include <cstddef>

// Problem constants
#define BB 4
#define SS 2048
#define DD 1024
#define HH 16
#define DHH 64
#define MTOT (BB*SS)   // 8192

// Scratch (__device__ globals per allocation rules)
__device__ float g_qkv [BB*HH*SS*DHH];   // [b,h,s,dh]  tf32, d pair-permuted
__device__ float g_qkvT[BB*HH*DHH*SS];   // [b,h,dh,s]  tf32, unpermuted d rows
__device__ float g_aout[MTOT*DD];        // [b*s, d]    tf32, d pair-permuted
__device__ float g_xr  [MTOT*DD];        // x,  tf32, k pair-permuted
__device__ float g_wqr [DD*DD];          // w_qkv, tf32, k pair-permuted
__device__ float g_wor [DD*DD];          // w_out, tf32, k pair-permuted

// ---------------------------------------------------------------------------
__device__ __forceinline__ uint32_t smem_u32(const void* p) {
    uint32_t a;
    asm("{ .reg .u64 t; cvta.to.shared.u64 t, %1; cvt.u32.u64 %0, t; }"
        : "=r"(a) : "l"(p));
    return a;
}
__device__ __forceinline__ void cp16(uint32_t s, const void* g) {
    asm volatile("cp.async.cg.shared.global [%0], [%1], 16;" :: "r"(s), "l"(g));
}
#define CP_COMMIT() asm volatile("cp.async.commit_group;" ::: "memory")
#define CP_WAIT(n)  asm volatile("cp.async.wait_group %0;" :: "n"(n) : "memory")

__device__ __forceinline__ uint32_t f2tf(float f) {
    uint32_t u;
    asm("cvt.rna.tf32.f32 %0, %1;" : "=r"(u) : "f"(f));
    return u;
}
__device__ __forceinline__ float tf_f(float f) { return __uint_as_float(f2tf(f)); }
__device__ __forceinline__ float ex2f(float f) {
    float r;
    asm("ex2.approx.ftz.f32 %0, %1;" : "=f"(r) : "f"(f));
    return r;
}

// D += A*B  (m16n8k8 tf32, fp32 accum)
__device__ __forceinline__ void mma8(float* c, const uint32_t* a,
                                     uint32_t b0, uint32_t b1) {
    asm volatile(
        "mma.sync.aligned.m16n8k8.row.col.f32.tf32.tf32.f32 "
        "{%0,%1,%2,%3}, {%4,%5,%6,%7}, {%8,%9}, {%0,%1,%2,%3};\n"
        : "+f"(c[0]), "+f"(c[1]), "+f"(c[2]), "+f"(c[3])
        : "r"(a[0]), "r"(a[1]), "r"(a[2]), "r"(a[3]), "r"(b0), "r"(b1));
}

// ---------------------------------------------------------------------------
// prep: tf32-round + pair-permute last-dim 8-blocks: orig k<4 -> 2k, else 2(k-4)+1
// ---------------------------------------------------------------------------
__global__ void prep_kernel(const float* __restrict__ src, float* __restrict__ dst,
                            int n4)
{
    int i = blockIdx.x * 256 + threadIdx.x;
    if (i >= n4) return;
    float4 v = *(const float4*)(src + (size_t)i * 4);
    int base = i * 4;
    int blk  = base & ~7;
    int o    = (base & 7) ? 1 : 0;   // e==0 -> even slots, e==4 -> odd slots
    dst[blk + o + 0] = tf_f(v.x);
    dst[blk + o + 2] = tf_f(v.y);
    dst[blk + o + 4] = tf_f(v.z);
    dst[blk + o + 6] = tf_f(v.w);
}

// ---------------------------------------------------------------------------
// tf32 GEMM: C[m,n] = sum_k A[m,k]*W[n,k], inputs pre-rounded + k-permuted.
// CTA 128x128, k-tile 32, 3-stage cp.async, XOR-swizzled stride-32 smem.
// 8 warps of 32m x 64n. MODE 0: -> g_qkv (d-permuted) + g_qkvT.
// MODE 1: -> out + bias (plain).
// ---------------------------------------------------------------------------
#define G_STAGE_BYTES 32768            // A 16KB + B 16KB
#define GEMM_SMEM_BYTES (3 * G_STAGE_BYTES)

template<int MODE>
__global__ __launch_bounds__(256, 2)
void tgemm(const float* __restrict__ A, const float* __restrict__ W,
           const float* __restrict__ bias, float* __restrict__ Cout)
{
    extern __shared__ __align__(128) float sg[];
    const uint32_t sbase = smem_u32(sg);

    const int tid = threadIdx.x;
    const int wid = tid >> 5, l = tid & 31;
    const int gy = l >> 2, gx = l & 3;
    const int wm = wid >> 1, wn = wid & 1;
    const int m0 = blockIdx.y * 128, n0 = blockIdx.x * 128;

    float acc[16][4];
    #pragma unroll
    for (int i = 0; i < 16; i++)
        #pragma unroll
        for (int j = 0; j < 4; j++) acc[i][j] = 0.f;

    auto copy_chunk = [&](int st, int kt) {
        const int k0 = kt * 32;
        const uint32_t dA = sbase + st * G_STAGE_BYTES;
        #pragma unroll
        for (int p = 0; p < 4; p++) {
            int e = p * 256 + tid;
            int row = e >> 3, c4 = e & 7;
            uint32_t off = row * 128 + ((c4 ^ (row & 7)) << 4);
            cp16(dA + off,         A + (size_t)(m0 + row) * 1024 + k0 + c4 * 4);
            cp16(dA + 16384 + off, W + (size_t)(n0 + row) * 1024 + k0 + c4 * 4);
        }
        CP_COMMIT();
    };

    const uint32_t mx = gy * 4;          // XOR swizzle mask (r&7 == gy for frag rows)

    copy_chunk(0, 0); copy_chunk(1, 1); copy_chunk(2, 2);

    for (int kt = 0; kt < 32; kt++) {
        const int st = kt - (kt / 3) * 3;
        CP_WAIT(2);
        __syncthreads();

        const float* as = sg + st * 8192;
        const float* bs = as + 4096;
        #pragma unroll
        for (int k8 = 0; k8 < 4; k8++) {
            const uint32_t col = (uint32_t)(k8 * 8 + 2 * gx) ^ mx;
            uint32_t a[2][4];
            #pragma unroll
            for (int fm = 0; fm < 2; fm++) {
                const int r = wm * 32 + fm * 16 + gy;
                float2 t0 = *(const float2*)&as[r * 32 + col];
                float2 t1 = *(const float2*)&as[(r + 8) * 32 + col];
                a[fm][0] = __float_as_uint(t0.x);
                a[fm][1] = __float_as_uint(t1.x);
                a[fm][2] = __float_as_uint(t0.y);
                a[fm][3] = __float_as_uint(t1.y);
            }
            #pragma unroll
            for (int fn = 0; fn < 8; fn++) {
                const int rn = wn * 64 + fn * 8 + gy;
                float2 b = *(const float2*)&bs[rn * 32 + col];
                mma8(acc[fn],     a[0], __float_as_uint(b.x), __float_as_uint(b.y));
                mma8(acc[8 + fn], a[1], __float_as_uint(b.x), __float_as_uint(b.y));
            }
        }
        __syncthreads();
        if (kt + 3 < 32) copy_chunk(st, kt + 3);
    }

    // Epilogue
    const int pos1 = (gx < 2) ? 4 * gx     : 4 * gx - 7;   // for element 2gx
    const int pos2 = (gx < 2) ? 4 * gx + 2 : 4 * gx - 5;   // for element 2gx+1
    #pragma unroll
    for (int fm = 0; fm < 2; fm++) {
        const int mrow = m0 + wm * 32 + fm * 16 + gy;
        #pragma unroll
        for (int fn = 0; fn < 8; fn++) {
            const float* cc = acc[fm * 8 + fn];
            const int n = n0 + wn * 64 + fn * 8 + 2 * gx;   // logical col
            if (MODE == 0) {
                float v0 = tf_f(cc[0]), v1 = tf_f(cc[1]);
                float v2 = tf_f(cc[2]), v3 = tf_f(cc[3]);
                const int h_ = n >> 6, dh = n & 63, blk = dh & ~7;
                const int b_ = mrow >> 11, s_ = mrow & 2047;
                float* d0 = g_qkv + ((size_t)(b_ * 16 + h_) * 2048 + s_) * 64 + blk;
                d0[pos1] = v0;  d0[pos2] = v1;
                d0[8 * 64 + pos1] = v2;  d0[8 * 64 + pos2] = v3;
                float* t0 = g_qkvT + ((size_t)(b_ * 16 + h_) * 64 + dh) * 2048 + s_;
                t0[0] = v0;  t0[2048] = v1;
                t0[8]  = v2; t0[2048 + 8] = v3;
            } else {
                float2 bv = *(const float2*)&bias[n];
                *(float2*)&Cout[(size_t)mrow * 1024 + n] =
                    make_float2(cc[0] + bv.x, cc[1] + bv.y);
                *(float2*)&Cout[(size_t)(mrow + 8) * 1024 + n] =
                    make_float2(cc[2] + bv.x, cc[3] + bv.y);
            }
        }
    }
}

// ---------------------------------------------------------------------------
// Flash attention: mma.sync tf32, exp2-domain fp32 EX2, ones-column l trick.
// 8 warps x 16 q-rows, kc-tile 64, double-buffered cp.async K / V^T tiles.
// K tile d-cols pair-permuted (matches g_qkv) -> LDS.64 B-frags.
// ---------------------------------------------------------------------------
// smem floats: Ks[2][64][68]=8704, Vt[2][72][68]=9792  -> 18496 floats
#define ATTN_SMEM_BYTES (18496 * 4)
#define EXP2SCALE 0.18033688011112042f   // 0.125 * log2(e)

__global__ __launch_bounds__(256, 1)
void attn_kernel()
{
    extern __shared__ float sm[];        // [K0][K1][V0][V1]
    const uint32_t sbase = smem_u32(sm);

    const int tid = threadIdx.x;
    const int wid = tid >> 5, l = tid & 31;
    const int gy = l >> 2, gx = l & 3;
    const int bh = blockIdx.y;
    const int q0 = blockIdx.x * 128;

    const float* Kg0 = g_qkv  + (size_t)bh * SS * DHH;
    const float* Vg0 = g_qkvT + (size_t)bh * DHH * SS;

    // ones-rows of Vt (rows 64..71, both buffers): row 64 = 1, rest 0
    {
        float* vt0 = sm + 8704;
        float* vt1 = vt0 + 4896;
        for (int i = tid; i < 8 * 68; i += 256) {
            int r = 64 + i / 68, c = i - (i / 68) * 68;
            vt0[r * 68 + c] = (r == 64) ? 1.f : 0.f;
            vt1[r * 68 + c] = (r == 64) ? 1.f : 0.f;
        }
    }

    // Q fragments: gmem d pair-permuted -> float2 gives (k, k+4)
    uint32_t qf[8][4];
    {
        const float* Qg = Kg0 + (size_t)(q0 + wid * 16) * 64;
        #pragma unroll
        for (int s = 0; s < 8; s++) {
            float2 t0 = *(const float2*)&Qg[gy * 64 + s * 8 + 2 * gx];
            float2 t1 = *(const float2*)&Qg[(gy + 8) * 64 + s * 8 + 2 * gx];
            qf[s][0] = __float_as_uint(t0.x);
            qf[s][1] = __float_as_uint(t1.x);
            qf[s][2] = __float_as_uint(t0.y);
            qf[s][3] = __float_as_uint(t1.y);
        }
    }

    float o[9][4];
    #pragma unroll
    for (int i = 0; i < 9; i++)
        #pragma unroll
        for (int j = 0; j < 4; j++) o[i][j] = 0.f;
    float m0 = -1e30f, m1 = -1e30f;      // exp2-domain running max

    auto stage_kv = [&](int ct, int st) {
        const float* Kg = Kg0 + (size_t)(ct * 64) * 64;
        const float* Vg = Vg0 + ct * 64;
        const uint32_t kd = sbase + st * 17408;            // Ks stage (bytes)
        const uint32_t vd = sbase + 34816 + st * 19584;    // Vt stage (bytes)
        #pragma unroll
        for (int p = 0; p < 4; p++) {
            int c = p * 256 + tid;
            int row = c >> 4, c4 = c & 15;
            cp16(kd + row * 272 + c4 * 16, Kg + row * 64 + c4 * 4);
            cp16(vd + row * 272 + c4 * 16, Vg + (size_t)row * SS + c4 * 4);
        }
        CP_COMMIT();
    };

    stage_kv(0, 0);

    for (int ct = 0; ct < 32; ct++) {
        const int st = ct & 1;
        if (ct + 1 < 32) { stage_kv(ct + 1, st ^ 1); CP_WAIT(1); }
        else             { CP_WAIT(0); }
        __syncthreads();

        const float* ks = sm + st * 4352;
        const float* vt = sm + 8704 + st * 4896;

        // S = Q K^T (exp2-domain scale)
        float sc[8][4];
        #pragma unroll
        for (int j = 0; j < 8; j++)
            #pragma unroll
            for (int v = 0; v < 4; v++) sc[j][v] = 0.f;

        #pragma unroll
        for (int s = 0; s < 8; s++) {
            #pragma unroll
            for (int j = 0; j < 8; j++) {
                float2 b = *(const float2*)&ks[(j * 8 + gy) * 68 + s * 8 + 2 * gx];
                mma8(sc[j], qf[s], __float_as_uint(b.x), __float_as_uint(b.y));
            }
        }
        #pragma unroll
        for (int j = 0; j < 8; j++)
            #pragma unroll
            for (int v = 0; v < 4; v++) sc[j][v] *= EXP2SCALE;

        // online softmax stats (exp2 domain)
        float mx0 = -1e30f, mx1 = -1e30f;
        #pragma unroll
        for (int j = 0; j < 8; j++) {
            mx0 = fmaxf(mx0, fmaxf(sc[j][0], sc[j][1]));
            mx1 = fmaxf(mx1, fmaxf(sc[j][2], sc[j][3]));
        }
        mx0 = fmaxf(mx0, __shfl_xor_sync(0xffffffffu, mx0, 1));
        mx0 = fmaxf(mx0, __shfl_xor_sync(0xffffffffu, mx0, 2));
        mx1 = fmaxf(mx1, __shfl_xor_sync(0xffffffffu, mx1, 1));
        mx1 = fmaxf(mx1, __shfl_xor_sync(0xffffffffu, mx1, 2));

        float mn0 = fmaxf(m0, mx0), mn1 = fmaxf(m1, mx1);
        float f0 = ex2f(m0 - mn0), f1 = ex2f(m1 - mn1);
        m0 = mn0; m1 = mn1;

        // p = 2^(s' - m') in fp32, then tf32-round for the mma
        uint32_t pt[8][4];
        #pragma unroll
        for (int j = 0; j < 8; j++) {
            pt[j][0] = f2tf(ex2f(sc[j][0] - m0));
            pt[j][1] = f2tf(ex2f(sc[j][1] - m0));
            pt[j][2] = f2tf(ex2f(sc[j][2] - m1));
            pt[j][3] = f2tf(ex2f(sc[j][3] - m1));
        }

        #pragma unroll
        for (int jd = 0; jd < 9; jd++) {
            o[jd][0] *= f0; o[jd][1] *= f0;
            o[jd][2] *= f1; o[jd][3] *= f1;
        }

        // O += P V  (9th n-group accumulates l via ones-row)
        #pragma unroll
        for (int g = 0; g < 8; g++) {
            const int src = (l & ~3) | (gx >> 1);
            uint32_t u0 = __shfl_sync(0xffffffffu, pt[g][0], src);
            uint32_t u1 = __shfl_sync(0xffffffffu, pt[g][1], src);
            uint32_t u2 = __shfl_sync(0xffffffffu, pt[g][2], src);
            uint32_t u3 = __shfl_sync(0xffffffffu, pt[g][3], src);
            uint32_t w0 = __shfl_sync(0xffffffffu, pt[g][0], src + 2);
            uint32_t w1 = __shfl_sync(0xffffffffu, pt[g][1], src + 2);
            uint32_t w2 = __shfl_sync(0xffffffffu, pt[g][2], src + 2);
            uint32_t w3 = __shfl_sync(0xffffffffu, pt[g][3], src + 2);
            uint32_t a[4];
            a[0] = (l & 1) ? u1 : u0;
            a[1] = (l & 1) ? u3 : u2;
            a[2] = (l & 1) ? w1 : w0;
            a[3] = (l & 1) ? w3 : w2;
            #pragma unroll
            for (int jd = 0; jd < 9; jd++) {
                uint32_t b0 = __float_as_uint(vt[(jd * 8 + gy) * 68 + g * 8 + gx]);
                uint32_t b1 = __float_as_uint(vt[(jd * 8 + gy) * 68 + g * 8 + gx + 4]);
                mma8(o[jd], a, b0, b1);
            }
        }
        __syncthreads();
    }

    // l from ones-column (col 64 = n-group 8 element 0, at gx==0 lanes)
    float l0 = __shfl_sync(0xffffffffu, o[8][0], l & ~3);
    float l1 = __shfl_sync(0xffffffffu, o[8][2], l & ~3);
    const float inv0 = 1.f / l0, inv1 = 1.f / l1;

    // Epilogue -> g_aout, d pair-permuted for GEMM2
    const int b_ = bh >> 4, h_ = bh & 15;
    const int r0 = q0 + wid * 16 + gy;
    float* out0 = g_aout + (size_t)(b_ * 2048 + r0) * 1024 + h_ * 64;
    float* out1 = out0 + (size_t)8 * 1024;
    const int pos1 = (gx < 2) ? 4 * gx     : 4 * gx - 7;
    const int pos2 = (gx < 2) ? 4 * gx + 2 : 4 * gx - 5;
    #pragma unroll
    for (int jd = 0; jd < 8; jd++) {
        out0[jd * 8 + pos1] = tf_f(o[jd][0] * inv0);
        out0[jd * 8 + pos2] = tf_f(o[jd][1] * inv0);
        out1[jd * 8 + pos1] = tf_f(o[jd][2] * inv1);
        out1[jd * 8 + pos2] = tf_f(o[jd][3] * inv1);
    }
}

// ---------------------------------------------------------------------------
extern "C" void kernel_launch(void* const* d_in, const int* in_sizes, int n_in,
                              void* d_out, int out_size)
{
    const float* x     = (const float*)d_in[0];
    const float* w_qkv = (const float*)d_in[1];
    const float* w_out = (const float*)d_in[2];
    const float* b_out = (const float*)d_in[3];
    float* out = (float*)d_out;

    cudaFuncSetAttribute(tgemm<0>, cudaFuncAttributeMaxDynamicSharedMemorySize,
                         GEMM_SMEM_BYTES);
    cudaFuncSetAttribute(tgemm<1>, cudaFuncAttributeMaxDynamicSharedMemorySize,
                         GEMM_SMEM_BYTES);
    cudaFuncSetAttribute(attn_kernel, cudaFuncAttributeMaxDynamicSharedMemorySize,
                         ATTN_SMEM_BYTES);

    // Resolve ALL device-symbol scratch addresses host-side (R4 bug: passing
    // g_aout directly gave the host shadow address -> GPU read zeros via ATS).
    float *xr, *wqr, *wor, *aoutp;
    cudaGetSymbolAddress((void**)&xr,    g_xr);
    cudaGetSymbolAddress((void**)&wqr,   g_wqr);
    cudaGetSymbolAddress((void**)&wor,   g_wor);
    cudaGetSymbolAddress((void**)&aoutp, g_aout);

    // pre-round + k-permute
    prep_kernel<<<(MTOT * DD / 4 + 255) / 256, 256>>>(x, xr, MTOT * DD / 4);
    prep_kernel<<<(DD * DD / 4 + 255) / 256, 256>>>(w_qkv, wqr, DD * DD / 4);
    prep_kernel<<<(DD * DD / 4 + 255) / 256, 256>>>(w_out, wor, DD * DD / 4);

    dim3 gemm_grid(1024 / 128, MTOT / 128);   // (8, 64)
    tgemm<0><<<gemm_grid, 256, GEMM_SMEM_BYTES>>>(xr, wqr, nullptr, nullptr);

    dim3 attn_grid(SS / 128, BB * HH);        // (16, 64)
    attn_kernel<<<attn_grid, 256, ATTN_SMEM_BYTES>>>();

    tgemm<1><<<gemm_grid, 256, GEMM_SMEM_BYTES>>>(aoutp, wor, b_out, out);
}